// round 9
// baseline (speedup 1.0000x reference)
#include <cuda_runtime.h>
#include <math.h>

#define C_DIM     128000
#define C_VEC     (C_DIM / 4)        // 32000 float4 per row
#define B_ROWS    2048
#define UPR       25                 // units per row
#define UNIT_V    (C_VEC / UPR)      // 1280 float4 per unit
#define NU_TOTAL  (B_ROWS * UPR)     // 51200 units
#define THREADS   256
#define NIT       (UNIT_V / THREADS) // 5 float4 iters per unit
#define GRID      1184               // 148 SMs * 8 CTAs = exactly one wave
#define BASE_U    (NU_TOTAL / GRID)  // 43
#define EXTRA     (NU_TOTAL - GRID * BASE_U)  // 288 blocks get 44 units

// 2 partial slots per row (a row of 25 units intersects <= 2 block ranges)
__device__ float4 g_partial[B_ROWS * 2];
// per-row arrival counter; reset by the finalizer -> graph-replay safe
__device__ unsigned int g_count[B_ROWS];

__device__ __forceinline__ int unit_to_block(int u) {
    const int cut = EXTRA * (BASE_U + 1);     // 288*44 = 12672
    return (u < cut) ? (u / (BASE_U + 1)) : (EXTRA + (u - cut) / BASE_U);
}

__device__ __forceinline__ void top2_val(float& m1, float& m2, float v) {
    float t = fminf(m1, v);
    m1 = fmaxf(m1, v);
    m2 = fmaxf(m2, t);
}

__global__ __launch_bounds__(THREADS, 8)
void persistent_kernel(const float* __restrict__ logits,
                       const int* __restrict__ y,
                       float* __restrict__ out) {
    const int b   = blockIdx.x;
    const int tid = threadIdx.x;
    const int wid = tid >> 5;
    const int lid = tid & 31;
    const unsigned FULL = 0xFFFFFFFFu;

    // this block's consecutive unit range [u0, u1)
    const int u0 = b * BASE_U + min(b, EXTRA);
    const int u1 = u0 + BASE_U + (b < EXTRA ? 1 : 0);

    __shared__ float s_sum[THREADS / 32];
    __shared__ float s_m1[THREADS / 32];
    __shared__ float s_m2[THREADS / 32];
    __shared__ unsigned int s_last;   // 0 = no finalize, else count of slots

    int u = u0;
    while (u < u1) {
        const int r = u / UPR;                     // row of this segment
        const int seg_end = min(u1, (r + 1) * UPR);
        const int nunits = seg_end - u;

        const float4* __restrict__ base =
            reinterpret_cast<const float4*>(logits + (size_t)r * C_DIM)
            + (u - r * UPR) * UNIT_V;

        // ---- accumulate the whole segment thread-locally (no reductions) --
        float sum = 0.0f;
        float m1 = -INFINITY, m2 = -INFINITY;
        for (int k = 0; k < nunits; k++) {
            const float4* pk = base + k * UNIT_V;
            #pragma unroll
            for (int it = 0; it < NIT; it++) {
                float4 v = pk[it * THREADS + tid];
                sum += __expf(v.x);
                sum += __expf(v.y);
                sum += __expf(v.z);
                sum += __expf(v.w);
                top2_val(m1, m2, v.x);
                top2_val(m1, m2, v.y);
                top2_val(m1, m2, v.z);
                top2_val(m1, m2, v.w);
            }
        }

        // ---- warp reduction ----
        #pragma unroll
        for (int off = 16; off > 0; off >>= 1) {
            sum += __shfl_xor_sync(FULL, sum, off);
            float om1 = __shfl_xor_sync(FULL, m1, off);
            float om2 = __shfl_xor_sync(FULL, m2, off);
            float nm1 = fmaxf(m1, om1);
            m2 = fmaxf(fminf(m1, om1), fmaxf(m2, om2));
            m1 = nm1;
        }

        // ---- cross-warp reduction ----
        if (lid == 0) { s_sum[wid] = sum; s_m1[wid] = m1; s_m2[wid] = m2; }
        __syncthreads();

        if (wid == 0) {
            const int nw = THREADS / 32;
            float fsum = (lid < nw) ? s_sum[lid] : 0.0f;
            float fm1  = (lid < nw) ? s_m1[lid]  : -INFINITY;
            float fm2  = (lid < nw) ? s_m2[lid]  : -INFINITY;

            #pragma unroll
            for (int off = nw / 2; off > 0; off >>= 1) {
                fsum += __shfl_xor_sync(FULL, fsum, off);
                float om1 = __shfl_xor_sync(FULL, fm1, off);
                float om2 = __shfl_xor_sync(FULL, fm2, off);
                float nm1 = fmaxf(fm1, om1);
                fm2 = fmaxf(fminf(fm1, om1), fmaxf(fm2, om2));
                fm1 = nm1;
            }

            if (lid == 0) {
                // which blocks cover this row?
                const int b_first = unit_to_block(r * UPR);
                const int b_last  = unit_to_block(r * UPR + (UPR - 1));
                const unsigned cnt = (unsigned)(b_last - b_first + 1); // 1 or 2
                const int slot = b - b_first;                          // 0 or 1

                g_partial[r * 2 + slot] = make_float4(fsum, fm1, fm2, 0.0f);
                unsigned int prev;
                asm volatile("atom.acq_rel.gpu.global.add.u32 %0, [%1], %2;"
                             : "=r"(prev)
                             : "l"(&g_count[r]), "r"(1u)
                             : "memory");
                s_last = (prev == cnt - 1u) ? cnt : 0u;
            }
        }
        __syncthreads();

        // ---- finalize this row (last arriver), warp 0 ----
        if (s_last && wid == 0 && lid == 0) {
            const unsigned cnt = s_last;
            float4 v0 = g_partial[r * 2 + 0];
            float tsum = v0.x, tm1 = v0.y, tm2 = v0.z;
            if (cnt == 2u) {
                float4 v1 = g_partial[r * 2 + 1];
                tsum += v1.x;
                float nm1 = fmaxf(tm1, v1.y);
                tm2 = fmaxf(fminf(tm1, v1.y), fmaxf(tm2, v1.z));
                tm1 = nm1;
            }

            int yv = y[r];
            if (yv < 0)      yv = 0;
            if (yv >= C_DIM) yv = C_DIM - 1;
            const float vy = __ldg(logits + (size_t)r * C_DIM + (size_t)yv);

            // y is argmax  <=>  logits[row][y] == global max (distinct values)
            const float first = (vy == tm1) ? tm2 : tm1;
            out[r] = first - logf(tsum - first);

            g_count[r] = 0u;   // reset for next graph replay
        }
        __syncthreads();

        u = seg_end;
    }
}

extern "C" void kernel_launch(void* const* d_in, const int* in_sizes, int n_in,
                              void* d_out, int out_size) {
    const float* logits = (const float*)d_in[0];
    const int*   y      = (const int*)d_in[1];
    float*       out    = (float*)d_out;
    (void)in_sizes; (void)n_in; (void)out_size;

    persistent_kernel<<<GRID, THREADS>>>(logits, y, out);
}

// round 10
// speedup vs baseline: 1.0370x; 1.0370x over previous
#include <cuda_runtime.h>
#include <math.h>

#define C_DIM     128000
#define C_VEC     (C_DIM / 4)        // 32000 float4 per row
#define B_ROWS    2048
#define SPLIT     5
#define CHUNK_V   (C_VEC / SPLIT)    // 6400 float4 per chunk
#define THREADS   256                // 25 iterations per producer block
#define NCONS     8                  // consumer blocks (8*256 = 2048 = one thread/row)

// partial per (row, split): x=sum_exp, y=m1, z=m2, w=unused
__device__ float4 g_partial[B_ROWS * SPLIT];
// per-row arrival counter; reset by the consumer -> graph-replay safe
__device__ unsigned int g_count[B_ROWS];

__device__ __forceinline__ void top2_val(float& m1, float& m2, float v) {
    float t = fminf(m1, v);
    m1 = fmaxf(m1, v);
    m2 = fmaxf(m2, t);
}

__global__ __launch_bounds__(THREADS, 8)
void stream_kernel(const float* __restrict__ logits,
                   const int* __restrict__ y,
                   float* __restrict__ out) {
    const int tid = threadIdx.x;
    const unsigned FULL = 0xFFFFFFFFu;

    // ================= consumer blocks: finalize rows as they complete ====
    if (blockIdx.x < NCONS) {
        const int row = blockIdx.x * THREADS + tid;   // one thread per row

        // spin until all SPLIT partials for this row are published
        unsigned c;
        for (;;) {
            asm volatile("ld.acquire.gpu.global.u32 %0, [%1];"
                         : "=r"(c) : "l"(&g_count[row]) : "memory");
            if (c >= SPLIT) break;
            __nanosleep(1024);
        }

        // partials are L2-hot (just written)
        float tsum = 0.0f;
        float tm1 = -INFINITY, tm2 = -INFINITY;
        #pragma unroll
        for (int s = 0; s < SPLIT; s++) {
            float4 v = g_partial[row * SPLIT + s];
            tsum += v.x;
            float nm1 = fmaxf(tm1, v.y);
            tm2 = fmaxf(fminf(tm1, v.y), fmaxf(tm2, v.z));
            tm1 = nm1;
        }

        int yv = y[row];
        if (yv < 0)      yv = 0;
        if (yv >= C_DIM) yv = C_DIM - 1;
        const float vy = __ldg(logits + (size_t)row * C_DIM + (size_t)yv);

        // y is argmax  <=>  logits[row][y] == global max (distinct values)
        const float first = (vy == tm1) ? tm2 : tm1;
        out[row] = first - logf(tsum - first);

        // reset for next graph replay (kernel boundary orders this)
        g_count[row] = 0u;
        return;
    }

    // ================= producer blocks: pure streaming (R3 phase1) ========
    const int unit  = blockIdx.x - NCONS;    // 0 .. B_ROWS*SPLIT-1
    const int row   = unit / SPLIT;
    const int split = unit - row * SPLIT;

    const float4* __restrict__ p =
        reinterpret_cast<const float4*>(logits + (size_t)row * C_DIM)
        + split * CHUNK_V;

    float sum = 0.0f;
    float m1 = -INFINITY, m2 = -INFINITY;

    #pragma unroll 5
    for (int j = tid; j < CHUNK_V; j += THREADS) {
        float4 v = p[j];
        sum += __expf(v.x);
        sum += __expf(v.y);
        sum += __expf(v.z);
        sum += __expf(v.w);
        top2_val(m1, m2, v.x);
        top2_val(m1, m2, v.y);
        top2_val(m1, m2, v.z);
        top2_val(m1, m2, v.w);
    }

    // ---- warp reduction ----
    #pragma unroll
    for (int off = 16; off > 0; off >>= 1) {
        sum += __shfl_xor_sync(FULL, sum, off);
        float om1 = __shfl_xor_sync(FULL, m1, off);
        float om2 = __shfl_xor_sync(FULL, m2, off);
        float nm1 = fmaxf(m1, om1);
        m2 = fmaxf(fminf(m1, om1), fmaxf(m2, om2));
        m1 = nm1;
    }

    // ---- cross-warp reduction ----
    __shared__ float s_sum[THREADS / 32];
    __shared__ float s_m1[THREADS / 32];
    __shared__ float s_m2[THREADS / 32];

    const int wid = tid >> 5;
    const int lid = tid & 31;
    if (lid == 0) { s_sum[wid] = sum; s_m1[wid] = m1; s_m2[wid] = m2; }
    __syncthreads();

    if (wid == 0) {
        const int nw = THREADS / 32;
        float fsum = (lid < nw) ? s_sum[lid] : 0.0f;
        float fm1  = (lid < nw) ? s_m1[lid]  : -INFINITY;
        float fm2  = (lid < nw) ? s_m2[lid]  : -INFINITY;

        #pragma unroll
        for (int off = nw / 2; off > 0; off >>= 1) {
            fsum += __shfl_xor_sync(FULL, fsum, off);
            float om1 = __shfl_xor_sync(FULL, fm1, off);
            float om2 = __shfl_xor_sync(FULL, fm2, off);
            float nm1 = fmaxf(fm1, om1);
            fm2 = fmaxf(fminf(fm1, om1), fmaxf(fm2, om2));
            fm1 = nm1;
        }

        if (lid == 0) {
            // publish partial, then release-increment the row counter.
            g_partial[unit] = make_float4(fsum, fm1, fm2, 0.0f);
            asm volatile("red.release.gpu.global.add.u32 [%0], %1;"
                         :: "l"(&g_count[row]), "r"(1u) : "memory");
        }
    }
}

extern "C" void kernel_launch(void* const* d_in, const int* in_sizes, int n_in,
                              void* d_out, int out_size) {
    const float* logits = (const float*)d_in[0];
    const int*   y      = (const int*)d_in[1];
    float*       out    = (float*)d_out;
    (void)in_sizes; (void)n_in; (void)out_size;

    stream_kernel<<<B_ROWS * SPLIT + NCONS, THREADS>>>(logits, y, out);
}